// round 1
// baseline (speedup 1.0000x reference)
#include <cuda_runtime.h>
#include <math_constants.h>

// Problem constants
#define B_   256
#define P_   128
#define KD   512
#define HE_  1024
#define HF_  512
#define HID_ 64
#define EMB  (KD + 2*HF_)   // 1536

// Scratch: per-batch bias vector bias[b][h] = query_b @ W1q + frame_b @ W1f
__device__ float g_bias[B_ * HID_];

// ---------------------------------------------------------------------------
// Kernel 1: bias[b][h] over the 2048-long (query||frame) vector.
// 128 blocks x 128 threads, 2 batches per block. W1qf chunks staged in smem.
// ---------------------------------------------------------------------------
__global__ void __launch_bounds__(128) bias_kernel(
    const float* __restrict__ query,
    const float* __restrict__ frame,
    const float* __restrict__ W1)
{
    const int b0  = blockIdx.x * 2;
    const int tid = threadIdx.x;
    const int bb  = tid >> 6;   // 0..1
    const int h   = tid & 63;

    __shared__ __align__(16) float xs[2][2048];       // 16 KB
    __shared__ __align__(16) float ws[128][HID_];     // 32 KB

    for (int i = tid; i < 2 * 2048; i += 128) {
        int bbi = i >> 11, j = i & 2047;
        xs[bbi][j] = (j < HE_) ? query[(b0 + bbi) * HE_ + j]
                               : frame[(b0 + bbi) * (2 * HF_) + (j - HE_)];
    }

    float acc = 0.f;
    for (int j0 = 0; j0 < 2048; j0 += 128) {
        __syncthreads();   // xs ready (iter 0) / previous chunk consumed
        const float4* src = reinterpret_cast<const float4*>(W1 + (KD + j0) * HID_);
        float4*       dst = reinterpret_cast<float4*>(&ws[0][0]);
        for (int i = tid; i < 128 * HID_ / 4; i += 128) dst[i] = src[i];
        __syncthreads();
        #pragma unroll 16
        for (int jj = 0; jj < 128; jj++)
            acc = fmaf(xs[bb][j0 + jj], ws[jj][h], acc);
    }
    g_bias[(b0 + bb) * HID_ + h] = acc;
}

// ---------------------------------------------------------------------------
// Kernel 2: per-batch scores + masked softmax.
// One CTA per batch, 256 threads. C-tile 128p x 64h, K=512 in 32-wide chunks.
// Each thread computes a 4p x 8h register micro-tile (32 FMA : 3 LDS.128).
// Epilogue: +bias, relu, dot W2, reduce over h, masked softmax -> weights.
// ---------------------------------------------------------------------------
__global__ void __launch_bounds__(256, 2) score_kernel(
    const float* __restrict__ keys,
    const int*   __restrict__ mask,
    const float* __restrict__ W1,
    const float* __restrict__ W2,
    float*       __restrict__ weights_out)
{
    const int b   = blockIdx.x;
    const int tid = threadIdx.x;
    const int tx  = tid & 7;    // h-block: h0 = tx*8
    const int ty  = tid >> 3;   // p-block: p0 = ty*4

    __shared__ __align__(16) float sA[32][132];   // [kk][p], pad keeps f4 align
    __shared__ __align__(16) float sB[32][HID_];  // [kk][h]
    __shared__ float bias_s[HID_];
    __shared__ float w2_s[HID_];
    __shared__ float red[P_][9];
    __shared__ float rtmp[8];

    if (tid < HID_) {
        bias_s[tid] = g_bias[b * HID_ + tid];
        w2_s[tid]   = W2[tid];
    }

    float acc[4][8];
    #pragma unroll
    for (int i = 0; i < 4; i++)
        #pragma unroll
        for (int j = 0; j < 8; j++) acc[i][j] = 0.f;

    const float* kb = keys + (size_t)b * P_ * KD;

    for (int k0 = 0; k0 < KD; k0 += 32) {
        // Stage A: keys[b, 0:128, k0:k0+32] -> sA[kk][p] (transposed)
        #pragma unroll
        for (int i = 0; i < 4; i++) {
            int fid = tid + 256 * i;          // float4 id, 0..1023
            int p   = fid >> 3;
            int kq  = (fid & 7) << 2;
            float4 v = *reinterpret_cast<const float4*>(kb + p * KD + k0 + kq);
            sA[kq + 0][p] = v.x; sA[kq + 1][p] = v.y;
            sA[kq + 2][p] = v.z; sA[kq + 3][p] = v.w;
        }
        // Stage B: W1k[k0:k0+32, 0:64] -> sB
        #pragma unroll
        for (int i = 0; i < 2; i++) {
            int fid = tid + 256 * i;          // float4 id, 0..511
            int kk  = fid >> 4;
            int h4  = (fid & 15) << 2;
            *reinterpret_cast<float4*>(&sB[kk][h4]) =
                *reinterpret_cast<const float4*>(W1 + (k0 + kk) * HID_ + h4);
        }
        __syncthreads();

        #pragma unroll 8
        for (int kk = 0; kk < 32; kk++) {
            float4 a  = *reinterpret_cast<const float4*>(&sA[kk][ty << 2]);
            float4 b0 = *reinterpret_cast<const float4*>(&sB[kk][tx << 3]);
            float4 b1 = *reinterpret_cast<const float4*>(&sB[kk][(tx << 3) + 4]);
            float av[4] = {a.x, a.y, a.z, a.w};
            float bv[8] = {b0.x, b0.y, b0.z, b0.w, b1.x, b1.y, b1.z, b1.w};
            #pragma unroll
            for (int i = 0; i < 4; i++)
                #pragma unroll
                for (int j = 0; j < 8; j++)
                    acc[i][j] = fmaf(av[i], bv[j], acc[i][j]);
        }
        __syncthreads();
    }

    // Epilogue: bias + relu + W2 partial dot (8 h values per thread)
    const int h0 = tx << 3;
    #pragma unroll
    for (int i = 0; i < 4; i++) {
        float s = 0.f;
        #pragma unroll
        for (int j = 0; j < 8; j++) {
            float v = acc[i][j] + bias_s[h0 + j];
            s = fmaf(fmaxf(v, 0.f), w2_s[h0 + j], s);
        }
        red[(ty << 2) + i][tx] = s;
    }
    __syncthreads();

    // scores for p = tid (first 128 threads), then masked softmax
    float score = -CUDART_INF_F;
    int   mv    = 0;
    if (tid < P_) {
        float s = 0.f;
        #pragma unroll
        for (int x = 0; x < 8; x++) s += red[tid][x];
        mv = mask[b * P_ + tid];
        score = mv ? s : -CUDART_INF_F;
    }
    // block max (warps 0-3 hold real data; 4-7 hold -inf, ignored)
    float m = score;
    #pragma unroll
    for (int o = 16; o > 0; o >>= 1)
        m = fmaxf(m, __shfl_xor_sync(0xffffffffu, m, o));
    if ((tid & 31) == 0) rtmp[tid >> 5] = m;
    __syncthreads();
    float mx = fmaxf(fmaxf(rtmp[0], rtmp[1]), fmaxf(rtmp[2], rtmp[3]));
    __syncthreads();   // protect rtmp before reuse for sum

    float e = (tid < P_ && mv) ? expf(score - mx) : 0.f;
    float s = e;
    #pragma unroll
    for (int o = 16; o > 0; o >>= 1)
        s += __shfl_xor_sync(0xffffffffu, s, o);
    if ((tid & 31) == 0) rtmp[tid >> 5] = s;
    __syncthreads();
    float total = rtmp[0] + rtmp[1] + rtmp[2] + rtmp[3];

    if (tid < P_) weights_out[b * P_ + tid] = e / total;
}

// ---------------------------------------------------------------------------
// Kernel 3: context[b] = weights_b @ keys_b (keys L2-resident from kernel 2),
// then concat frame -> embeddings.
// ---------------------------------------------------------------------------
__global__ void __launch_bounds__(256) context_kernel(
    const float* __restrict__ keys,
    const float* __restrict__ frame,
    const float* __restrict__ weights,
    float*       __restrict__ out)
{
    const int b   = blockIdx.x;
    const int tid = threadIdx.x;
    __shared__ float w[P_];
    if (tid < P_) w[tid] = weights[b * P_ + tid];
    __syncthreads();

    const float* kb = keys + (size_t)b * P_ * KD;
    float a0 = 0.f, a1 = 0.f;
    #pragma unroll 8
    for (int p = 0; p < P_; p++) {
        float wp = w[p];
        a0 = fmaf(wp, kb[p * KD + tid],       a0);
        a1 = fmaf(wp, kb[p * KD + tid + 256], a1);
    }
    float* ob = out + (size_t)b * EMB;
    ob[tid]       = a0;
    ob[tid + 256] = a1;
    #pragma unroll
    for (int i = 0; i < 4; i++)
        ob[KD + tid + 256 * i] = frame[b * (2 * HF_) + tid + 256 * i];
}

// ---------------------------------------------------------------------------
extern "C" void kernel_launch(void* const* d_in, const int* in_sizes, int n_in,
                              void* d_out, int out_size)
{
    const float* query = (const float*)d_in[0];   // (256,1,1024)
    const float* keys  = (const float*)d_in[1];   // (256,128,512)
    const float* frame = (const float*)d_in[2];   // (256,1,1024)
    const int*   mask  = (const int*)  d_in[3];   // (256,128)
    const float* W1    = (const float*)d_in[4];   // (2560,64)
    const float* W2    = (const float*)d_in[5];   // (64,1)

    float* out     = (float*)d_out;
    float* weights = out + (size_t)B_ * EMB;      // embeddings first, weights after

    bias_kernel   <<<B_ / 2, 128>>>(query, frame, W1);
    score_kernel  <<<B_,     256>>>(keys, mask, W1, W2, weights);
    context_kernel<<<B_,     256>>>(keys, frame, weights, out);
}

// round 2
// speedup vs baseline: 1.2216x; 1.2216x over previous
#include <cuda_runtime.h>
#include <math_constants.h>

// Problem constants
#define B_   256
#define P_   128
#define KD   512
#define HE_  1024
#define HF_  512
#define HID_ 64
#define EMB  (KD + 2*HF_)   // 1536

#define KC_  16   // k-chunks of 128 over the 2048 (query||frame) dim
#define BG_  8    // batch groups of 32

typedef unsigned long long u64;

// Scratch: split-k partials for bias[b][h] = x_b @ W1qf
__device__ float g_part[KC_][B_][HID_];

__device__ __forceinline__ u64 ffma2(u64 a, u64 b, u64 c) {
    u64 d;
    asm("fma.rn.f32x2 %0, %1, %2, %3;" : "=l"(d) : "l"(a), "l"(b), "l"(c));
    return d;
}
__device__ __forceinline__ u64 dup2(float x) {
    u64 d; unsigned r = __float_as_uint(x);
    asm("mov.b64 %0, {%1, %1};" : "=l"(d) : "r"(r));
    return d;
}
__device__ __forceinline__ void unpack2(u64 v, float& lo, float& hi) {
    unsigned l, h;
    asm("mov.b64 {%0, %1}, %2;" : "=r"(l), "=r"(h) : "l"(v));
    lo = __uint_as_float(l); hi = __uint_as_float(h);
}

// ---------------------------------------------------------------------------
// Kernel 1: split-K bias partials. Block (kc, bg): 128 k-rows x 32 batches.
// ---------------------------------------------------------------------------
__global__ void __launch_bounds__(256) bias_kernel(
    const float* __restrict__ query,
    const float* __restrict__ frame,
    const float* __restrict__ W1)
{
    const int kc = blockIdx.x;
    const int bg = blockIdx.y;
    const int j0 = kc * 128;        // row within 2048-dim (query||frame)
    const int b0 = bg * 32;
    const int tid = threadIdx.x;

    __shared__ __align__(16) float ws[128][HID_];   // 32 KB
    __shared__ __align__(16) float xs[32][128];     // 16 KB

    // stage W1 chunk: rows (KD + j0) .. +127
    {
        const float4* src = reinterpret_cast<const float4*>(W1 + (size_t)(KD + j0) * HID_);
        float4* dst = reinterpret_cast<float4*>(&ws[0][0]);
        #pragma unroll
        for (int i = 0; i < 8; i++) dst[tid + 256 * i] = src[tid + 256 * i];
    }
    // stage X chunk: both query and frame have row stride 1024 floats
    {
        const float* xsrc = (j0 < HE_) ? (query + (size_t)b0 * HE_ + j0)
                                       : (frame + (size_t)b0 * (2 * HF_) + (j0 - HE_));
        #pragma unroll
        for (int i = 0; i < 4; i++) {
            int fid = tid + 256 * i;        // 0..1023 float4 ids (32 rows x 32 f4)
            int r = fid >> 5, c4 = (fid & 31) << 2;
            *reinterpret_cast<float4*>(&xs[r][c4]) =
                *reinterpret_cast<const float4*>(xsrc + (size_t)r * 1024 + c4);
        }
    }
    __syncthreads();

    const int h  = tid & 63;
    const int bq = tid >> 6;        // 0..3 -> batches bq*8..+7

    float acc[8];
    #pragma unroll
    for (int i = 0; i < 8; i++) acc[i] = 0.f;

    for (int kk0 = 0; kk0 < 128; kk0 += 4) {
        float w0 = ws[kk0 + 0][h], w1 = ws[kk0 + 1][h];
        float w2 = ws[kk0 + 2][h], w3 = ws[kk0 + 3][h];
        #pragma unroll
        for (int i = 0; i < 8; i++) {
            float4 x = *reinterpret_cast<const float4*>(&xs[bq * 8 + i][kk0]);
            acc[i] = fmaf(x.x, w0, acc[i]);
            acc[i] = fmaf(x.y, w1, acc[i]);
            acc[i] = fmaf(x.z, w2, acc[i]);
            acc[i] = fmaf(x.w, w3, acc[i]);
        }
    }
    #pragma unroll
    for (int i = 0; i < 8; i++)
        g_part[kc][b0 + bq * 8 + i][h] = acc[i];
}

// ---------------------------------------------------------------------------
// Kernel 2: per-batch scores + masked softmax + context (fused).
// One CTA per batch, 256 threads. C-tile 128p x 64h via packed f32x2 FMA:
// each thread owns a 4p x 8h micro-tile held as 16 f32x2 accumulators.
// ---------------------------------------------------------------------------
__global__ void __launch_bounds__(256, 2) score_kernel(
    const float* __restrict__ keys,
    const float* __restrict__ frame,
    const int*   __restrict__ mask,
    const float* __restrict__ W1,
    const float* __restrict__ W2,
    float*       __restrict__ out)
{
    const int b   = blockIdx.x;
    const int tid = threadIdx.x;
    const int tx  = tid & 7;    // h-block: h0 = tx*8
    const int ty  = tid >> 3;   // p-block: p0 = ty*4

    __shared__ __align__(16) float sA[32][132];   // [kk][p]
    __shared__ __align__(16) float sB[32][HID_];  // [kk][h]
    __shared__ float bias_s[HID_];
    __shared__ float w2_s[HID_];
    __shared__ float red[P_][9];
    __shared__ float rtmp[8];
    __shared__ float wsm[P_];

    if (tid < HID_) {
        float s = 0.f;
        #pragma unroll
        for (int c = 0; c < KC_; c++) s += g_part[c][b][tid];
        bias_s[tid] = s;
        w2_s[tid]   = W2[tid];
    }

    u64 acc2[4][4];
    #pragma unroll
    for (int i = 0; i < 4; i++)
        #pragma unroll
        for (int j = 0; j < 4; j++) acc2[i][j] = 0ull;

    const float* kb = keys + (size_t)b * P_ * KD;

    for (int k0 = 0; k0 < KD; k0 += 32) {
        // Stage A: keys[b, 0:128, k0:k0+32] -> sA[kk][p] (transposed)
        #pragma unroll
        for (int i = 0; i < 4; i++) {
            int fid = tid + 256 * i;          // float4 id, 0..1023
            int p   = fid >> 3;
            int kq  = (fid & 7) << 2;
            float4 v = *reinterpret_cast<const float4*>(kb + (size_t)p * KD + k0 + kq);
            sA[kq + 0][p] = v.x; sA[kq + 1][p] = v.y;
            sA[kq + 2][p] = v.z; sA[kq + 3][p] = v.w;
        }
        // Stage B: W1k[k0:k0+32, 0:64] -> sB
        #pragma unroll
        for (int i = 0; i < 2; i++) {
            int fid = tid + 256 * i;          // float4 id, 0..511
            int kk  = fid >> 4;
            int h4  = (fid & 15) << 2;
            *reinterpret_cast<float4*>(&sB[kk][h4]) =
                *reinterpret_cast<const float4*>(W1 + (size_t)(k0 + kk) * HID_ + h4);
        }
        __syncthreads();

        #pragma unroll 8
        for (int kk = 0; kk < 32; kk++) {
            float4 a = *reinterpret_cast<const float4*>(&sA[kk][ty << 2]);
            u64 av[4] = {dup2(a.x), dup2(a.y), dup2(a.z), dup2(a.w)};
            const u64* brow = reinterpret_cast<const u64*>(&sB[kk][tx << 3]);
            u64 bv0 = brow[0], bv1 = brow[1], bv2 = brow[2], bv3 = brow[3];
            #pragma unroll
            for (int i = 0; i < 4; i++) {
                acc2[i][0] = ffma2(av[i], bv0, acc2[i][0]);
                acc2[i][1] = ffma2(av[i], bv1, acc2[i][1]);
                acc2[i][2] = ffma2(av[i], bv2, acc2[i][2]);
                acc2[i][3] = ffma2(av[i], bv3, acc2[i][3]);
            }
        }
        __syncthreads();
    }

    // Epilogue: bias + relu + W2 partial dot (8 h values per thread)
    const int h0 = tx << 3;
    #pragma unroll
    for (int i = 0; i < 4; i++) {
        float s = 0.f;
        #pragma unroll
        for (int j = 0; j < 4; j++) {
            float lo, hi;
            unpack2(acc2[i][j], lo, hi);
            float v0 = lo + bias_s[h0 + 2 * j];
            float v1 = hi + bias_s[h0 + 2 * j + 1];
            s = fmaf(fmaxf(v0, 0.f), w2_s[h0 + 2 * j],     s);
            s = fmaf(fmaxf(v1, 0.f), w2_s[h0 + 2 * j + 1], s);
        }
        red[(ty << 2) + i][tx] = s;
    }
    __syncthreads();

    // scores for p = tid (first 128 threads), then masked softmax
    float score = -CUDART_INF_F;
    int   mv    = 0;
    if (tid < P_) {
        float s = 0.f;
        #pragma unroll
        for (int x = 0; x < 8; x++) s += red[tid][x];
        mv = mask[b * P_ + tid];
        score = mv ? s : -CUDART_INF_F;
    }
    float m = score;
    #pragma unroll
    for (int o = 16; o > 0; o >>= 1)
        m = fmaxf(m, __shfl_xor_sync(0xffffffffu, m, o));
    if ((tid & 31) == 0) rtmp[tid >> 5] = m;
    __syncthreads();
    float mx = fmaxf(fmaxf(rtmp[0], rtmp[1]), fmaxf(rtmp[2], rtmp[3]));
    __syncthreads();   // protect rtmp before reuse for sum

    float e = (tid < P_ && mv) ? expf(score - mx) : 0.f;
    float s = e;
    #pragma unroll
    for (int o = 16; o > 0; o >>= 1)
        s += __shfl_xor_sync(0xffffffffu, s, o);
    if ((tid & 31) == 0) rtmp[tid >> 5] = s;
    __syncthreads();
    float total = rtmp[0] + rtmp[1] + rtmp[2] + rtmp[3];

    float* weights_out = out + (size_t)B_ * EMB;
    if (tid < P_) {
        float wv = e / total;
        weights_out[b * P_ + tid] = wv;
        wsm[tid] = wv;
    }
    __syncthreads();

    // Fused context: thread t -> cols 2t, 2t+1 (keys are L2-hot)
    float cx = 0.f, cy = 0.f;
    const float* kcol = kb + 2 * tid;
    #pragma unroll 8
    for (int p = 0; p < P_; p++) {
        float2 kv = *reinterpret_cast<const float2*>(kcol + (size_t)p * KD);
        float wp = wsm[p];
        cx = fmaf(wp, kv.x, cx);
        cy = fmaf(wp, kv.y, cy);
    }
    float* ob = out + (size_t)b * EMB;
    *reinterpret_cast<float2*>(ob + 2 * tid) = make_float2(cx, cy);

    // frame concat: 1024 floats = 256 float4, one per thread
    *reinterpret_cast<float4*>(ob + KD + 4 * tid) =
        *reinterpret_cast<const float4*>(frame + (size_t)b * (2 * HF_) + 4 * tid);
}

// ---------------------------------------------------------------------------
extern "C" void kernel_launch(void* const* d_in, const int* in_sizes, int n_in,
                              void* d_out, int out_size)
{
    const float* query = (const float*)d_in[0];   // (256,1,1024)
    const float* keys  = (const float*)d_in[1];   // (256,128,512)
    const float* frame = (const float*)d_in[2];   // (256,1,1024)
    const int*   mask  = (const int*)  d_in[3];   // (256,128)
    const float* W1    = (const float*)d_in[4];   // (2560,64)
    const float* W2    = (const float*)d_in[5];   // (64,1)

    float* out = (float*)d_out;

    dim3 bgrid(KC_, BG_);
    bias_kernel <<<bgrid, 256>>>(query, frame, W1);
    score_kernel<<<B_,    256>>>(keys, frame, mask, W1, W2, out);
}

// round 4
// speedup vs baseline: 1.6987x; 1.3906x over previous
#include <cuda_runtime.h>
#include <math_constants.h>

// Problem constants
#define B_   256
#define P_   128
#define KD   512
#define HE_  1024
#define HF_  512
#define HID_ 64
#define EMB  (KD + 2*HF_)   // 1536

#define KC_  16   // k-chunks of 128 over the 2048 (query||frame) dim
#define BG_  8    // batch groups of 32

typedef unsigned long long u64;

// Scratch: split-k partials for bias[b][h] = x_b @ W1qf
__device__ float g_part[KC_][B_][HID_];

__device__ __forceinline__ u64 ffma2(u64 a, u64 b, u64 c) {
    u64 d;
    asm("fma.rn.f32x2 %0, %1, %2, %3;" : "=l"(d) : "l"(a), "l"(b), "l"(c));
    return d;
}
__device__ __forceinline__ u64 dup2(float x) {
    u64 d; unsigned r = __float_as_uint(x);
    asm("mov.b64 %0, {%1, %1};" : "=l"(d) : "r"(r));
    return d;
}
__device__ __forceinline__ void unpack2(u64 v, float& lo, float& hi) {
    unsigned l, h;
    asm("mov.b64 {%0, %1}, %2;" : "=r"(l), "=r"(h) : "l"(v));
    lo = __uint_as_float(l); hi = __uint_as_float(h);
}

// ---------------------------------------------------------------------------
// Kernel 1: split-K bias partials. Block (kc, bg): 128 k-rows x 32 batches.
// ---------------------------------------------------------------------------
__global__ void __launch_bounds__(256) bias_kernel(
    const float* __restrict__ query,
    const float* __restrict__ frame,
    const float* __restrict__ W1)
{
    const int kc = blockIdx.x;
    const int bg = blockIdx.y;
    const int j0 = kc * 128;
    const int b0 = bg * 32;
    const int tid = threadIdx.x;

    __shared__ __align__(16) float ws[128][HID_];
    __shared__ __align__(16) float xs[32][128];

    {
        const float4* src = reinterpret_cast<const float4*>(W1 + (size_t)(KD + j0) * HID_);
        float4* dst = reinterpret_cast<float4*>(&ws[0][0]);
        #pragma unroll
        for (int i = 0; i < 8; i++) dst[tid + 256 * i] = src[tid + 256 * i];
    }
    {
        const float* xsrc = (j0 < HE_) ? (query + (size_t)b0 * HE_ + j0)
                                       : (frame + (size_t)b0 * (2 * HF_) + (j0 - HE_));
        #pragma unroll
        for (int i = 0; i < 4; i++) {
            int fid = tid + 256 * i;
            int r = fid >> 5, c4 = (fid & 31) << 2;
            *reinterpret_cast<float4*>(&xs[r][c4]) =
                *reinterpret_cast<const float4*>(xsrc + (size_t)r * 1024 + c4);
        }
    }
    __syncthreads();

    const int h  = tid & 63;
    const int bq = tid >> 6;

    float acc[8];
    #pragma unroll
    for (int i = 0; i < 8; i++) acc[i] = 0.f;

    for (int kk0 = 0; kk0 < 128; kk0 += 4) {
        float w0 = ws[kk0 + 0][h], w1 = ws[kk0 + 1][h];
        float w2 = ws[kk0 + 2][h], w3 = ws[kk0 + 3][h];
        #pragma unroll
        for (int i = 0; i < 8; i++) {
            float4 x = *reinterpret_cast<const float4*>(&xs[bq * 8 + i][kk0]);
            acc[i] = fmaf(x.x, w0, acc[i]);
            acc[i] = fmaf(x.y, w1, acc[i]);
            acc[i] = fmaf(x.z, w2, acc[i]);
            acc[i] = fmaf(x.w, w3, acc[i]);
        }
    }
    #pragma unroll
    for (int i = 0; i < 8; i++)
        g_part[kc][b0 + bq * 8 + i][h] = acc[i];
}

// ---------------------------------------------------------------------------
// Kernel 2: per-batch scores + masked softmax + context (fused).
// One CTA per batch, 128 threads. C-tile 128p x 64h; each thread owns an
// 8p x 8h micro-tile as 32 f32x2 accumulators. 64 FMA per 64B of LDS.
// ---------------------------------------------------------------------------
__global__ void __launch_bounds__(128, 4) score_kernel(
    const float* __restrict__ keys,
    const float* __restrict__ frame,
    const int*   __restrict__ mask,
    const float* __restrict__ W1,
    const float* __restrict__ W2,
    float*       __restrict__ out)
{
    const int b   = blockIdx.x;
    const int tid = threadIdx.x;
    const int tx  = tid & 7;    // h-block: h0 = tx*8
    const int ty  = tid >> 3;   // p-block: p0 = ty*8

    __shared__ __align__(16) float sA[32][132];   // [kk][p] transposed keys
    __shared__ __align__(16) float sB[32][HID_];  // [kk][h]
    __shared__ float bias_s[HID_];
    __shared__ float w2_s[HID_];
    __shared__ float red[P_][9];
    __shared__ float rtmp[4];
    __shared__ float wsm[P_];

    if (tid < HID_) {
        float s = 0.f;
        #pragma unroll
        for (int c = 0; c < KC_; c++) s += g_part[c][b][tid];
        bias_s[tid] = s;
        w2_s[tid]   = W2[tid];
    }

    u64 acc2[8][4];
    #pragma unroll
    for (int i = 0; i < 8; i++)
        #pragma unroll
        for (int j = 0; j < 4; j++) acc2[i][j] = 0ull;

    const float* kb = keys + (size_t)b * P_ * KD;

    for (int k0 = 0; k0 < KD; k0 += 32) {
        // Stage A: keys[b, 0:128, k0:+32] -> sA[kk][p] (transposed)
        #pragma unroll
        for (int i = 0; i < 8; i++) {
            int fid = tid + 128 * i;          // float4 id, 0..1023
            int p   = fid >> 3;
            int kq  = (fid & 7) << 2;
            float4 v = *reinterpret_cast<const float4*>(kb + (size_t)p * KD + k0 + kq);
            sA[kq + 0][p] = v.x; sA[kq + 1][p] = v.y;
            sA[kq + 2][p] = v.z; sA[kq + 3][p] = v.w;
        }
        // Stage B: W1k[k0:+32, 0:64] -> sB. 32 rows x 16 float4 = 512 float4,
        // 128 threads -> 4 iterations (FIX: round-3 bug covered only kk 0..7).
        #pragma unroll
        for (int i = 0; i < 4; i++) {
            int fid = tid + 128 * i;          // 0..511
            int kk  = fid >> 4;
            int h4  = (fid & 15) << 2;
            *reinterpret_cast<float4*>(&sB[kk][h4]) =
                *reinterpret_cast<const float4*>(W1 + (size_t)(k0 + kk) * HID_ + h4);
        }
        __syncthreads();

        #pragma unroll 4
        for (int kk = 0; kk < 32; kk++) {
            float4 a0 = *reinterpret_cast<const float4*>(&sA[kk][ty << 3]);
            float4 a1 = *reinterpret_cast<const float4*>(&sA[kk][(ty << 3) + 4]);
            ulonglong2 bq0 = *reinterpret_cast<const ulonglong2*>(&sB[kk][tx << 3]);
            ulonglong2 bq1 = *reinterpret_cast<const ulonglong2*>(&sB[kk][(tx << 3) + 4]);
            u64 bv0 = bq0.x, bv1 = bq0.y, bv2 = bq1.x, bv3 = bq1.y;
            u64 av[8] = {dup2(a0.x), dup2(a0.y), dup2(a0.z), dup2(a0.w),
                         dup2(a1.x), dup2(a1.y), dup2(a1.z), dup2(a1.w)};
            #pragma unroll
            for (int i = 0; i < 8; i++) {
                acc2[i][0] = ffma2(av[i], bv0, acc2[i][0]);
                acc2[i][1] = ffma2(av[i], bv1, acc2[i][1]);
                acc2[i][2] = ffma2(av[i], bv2, acc2[i][2]);
                acc2[i][3] = ffma2(av[i], bv3, acc2[i][3]);
            }
        }
        __syncthreads();
    }

    // Epilogue: bias + relu + W2 partial dot (8 h values per thread, 8 p's)
    const int h0 = tx << 3;
    #pragma unroll
    for (int i = 0; i < 8; i++) {
        float s = 0.f;
        #pragma unroll
        for (int j = 0; j < 4; j++) {
            float lo, hi;
            unpack2(acc2[i][j], lo, hi);
            float v0 = lo + bias_s[h0 + 2 * j];
            float v1 = hi + bias_s[h0 + 2 * j + 1];
            s = fmaf(fmaxf(v0, 0.f), w2_s[h0 + 2 * j],     s);
            s = fmaf(fmaxf(v1, 0.f), w2_s[h0 + 2 * j + 1], s);
        }
        red[(ty << 3) + i][tx] = s;
    }
    __syncthreads();

    // scores for p = tid (all 128 threads), masked softmax
    float s = 0.f;
    #pragma unroll
    for (int x = 0; x < 8; x++) s += red[tid][x];
    int mv = mask[b * P_ + tid];
    float score = mv ? s : -CUDART_INF_F;

    float m = score;
    #pragma unroll
    for (int o = 16; o > 0; o >>= 1)
        m = fmaxf(m, __shfl_xor_sync(0xffffffffu, m, o));
    if ((tid & 31) == 0) rtmp[tid >> 5] = m;
    __syncthreads();
    float mx = fmaxf(fmaxf(rtmp[0], rtmp[1]), fmaxf(rtmp[2], rtmp[3]));
    __syncthreads();

    float e = mv ? expf(score - mx) : 0.f;
    float ssum = e;
    #pragma unroll
    for (int o = 16; o > 0; o >>= 1)
        ssum += __shfl_xor_sync(0xffffffffu, ssum, o);
    if ((tid & 31) == 0) rtmp[tid >> 5] = ssum;
    __syncthreads();
    float total = rtmp[0] + rtmp[1] + rtmp[2] + rtmp[3];

    float* weights_out = out + (size_t)B_ * EMB;
    {
        float wv = e / total;
        weights_out[b * P_ + tid] = wv;
        wsm[tid] = wv;
    }
    __syncthreads();

    // Fused context: thread t -> cols 4t..4t+3 (keys L2-hot from GEMM pass)
    float4 c = make_float4(0.f, 0.f, 0.f, 0.f);
    const float* kcol = kb + 4 * tid;
    #pragma unroll 8
    for (int p = 0; p < P_; p++) {
        float4 kv = *reinterpret_cast<const float4*>(kcol + (size_t)p * KD);
        float wp = wsm[p];
        c.x = fmaf(wp, kv.x, c.x);
        c.y = fmaf(wp, kv.y, c.y);
        c.z = fmaf(wp, kv.z, c.z);
        c.w = fmaf(wp, kv.w, c.w);
    }
    float* ob = out + (size_t)b * EMB;
    *reinterpret_cast<float4*>(ob + 4 * tid) = c;

    // frame concat: 1024 floats = 256 float4, two per thread
    const float* fb = frame + (size_t)b * (2 * HF_);
    *reinterpret_cast<float4*>(ob + KD + 4 * tid) =
        *reinterpret_cast<const float4*>(fb + 4 * tid);
    *reinterpret_cast<float4*>(ob + KD + 512 + 4 * tid) =
        *reinterpret_cast<const float4*>(fb + 512 + 4 * tid);
}

// ---------------------------------------------------------------------------
extern "C" void kernel_launch(void* const* d_in, const int* in_sizes, int n_in,
                              void* d_out, int out_size)
{
    const float* query = (const float*)d_in[0];   // (256,1,1024)
    const float* keys  = (const float*)d_in[1];   // (256,128,512)
    const float* frame = (const float*)d_in[2];   // (256,1,1024)
    const int*   mask  = (const int*)  d_in[3];   // (256,128)
    const float* W1    = (const float*)d_in[4];   // (2560,64)
    const float* W2    = (const float*)d_in[5];   // (64,1)

    float* out = (float*)d_out;

    dim3 bgrid(KC_, BG_);
    bias_kernel <<<bgrid, 256>>>(query, frame, W1);
    score_kernel<<<B_,    128>>>(keys, frame, mask, W1, W2, out);
}

// round 13
// speedup vs baseline: 1.8177x; 1.0700x over previous
#include <cuda_runtime.h>
#include <math_constants.h>

// Problem constants
#define B_   256
#define P_   128
#define KD   512
#define HE_  1024
#define HF_  512
#define HID_ 64
#define EMB  (KD + 2*HF_)   // 1536

#define KC_  16   // bias split-k chunks of 128 over 2048
#define BG_  8

typedef unsigned long long u64;
typedef unsigned int u32;

// Scratch: split-k partials for bias[b][h] = x_b @ W1qf
__device__ float g_part[KC_][B_][HID_];

__device__ __forceinline__ u64 ffma2(u64 a, u64 b, u64 c) {
    u64 d;
    asm("fma.rn.f32x2 %0, %1, %2, %3;" : "=l"(d) : "l"(a), "l"(b), "l"(c));
    return d;
}
__device__ __forceinline__ u64 dup2(float x) {
    u64 d; unsigned r = __float_as_uint(x);
    asm("mov.b64 %0, {%1, %1};" : "=l"(d) : "r"(r));
    return d;
}
__device__ __forceinline__ void unpack2(u64 v, float& lo, float& hi) {
    unsigned l, h;
    asm("mov.b64 {%0, %1}, %2;" : "=r"(l), "=r"(h) : "l"(v));
    lo = __uint_as_float(l); hi = __uint_as_float(h);
}

// ---------------------------------------------------------------------------
// Kernel 1: split-K bias partials (unchanged — proven, ~3us).
// ---------------------------------------------------------------------------
__global__ void __launch_bounds__(256) bias_kernel(
    const float* __restrict__ query,
    const float* __restrict__ frame,
    const float* __restrict__ W1)
{
    const int kc = blockIdx.x;
    const int bg = blockIdx.y;
    const int j0 = kc * 128;
    const int b0 = bg * 32;
    const int tid = threadIdx.x;

    __shared__ __align__(16) float ws[128][HID_];
    __shared__ __align__(16) float xs[32][128];

    {
        const float4* src = reinterpret_cast<const float4*>(W1 + (size_t)(KD + j0) * HID_);
        float4* dst = reinterpret_cast<float4*>(&ws[0][0]);
        #pragma unroll
        for (int i = 0; i < 8; i++) dst[tid + 256 * i] = src[tid + 256 * i];
    }
    {
        const float* xsrc = (j0 < HE_) ? (query + (size_t)b0 * HE_ + j0)
                                       : (frame + (size_t)b0 * (2 * HF_) + (j0 - HE_));
        #pragma unroll
        for (int i = 0; i < 4; i++) {
            int fid = tid + 256 * i;
            int r = fid >> 5, c4 = (fid & 31) << 2;
            *reinterpret_cast<float4*>(&xs[r][c4]) =
                *reinterpret_cast<const float4*>(xsrc + (size_t)r * 1024 + c4);
        }
    }
    __syncthreads();

    const int h  = tid & 63;
    const int bq = tid >> 6;

    float acc[8];
    #pragma unroll
    for (int i = 0; i < 8; i++) acc[i] = 0.f;

    for (int kk0 = 0; kk0 < 128; kk0 += 4) {
        float w0 = ws[kk0 + 0][h], w1 = ws[kk0 + 1][h];
        float w2 = ws[kk0 + 2][h], w3 = ws[kk0 + 3][h];
        #pragma unroll
        for (int i = 0; i < 8; i++) {
            float4 x = *reinterpret_cast<const float4*>(&xs[bq * 8 + i][kk0]);
            acc[i] = fmaf(x.x, w0, acc[i]);
            acc[i] = fmaf(x.y, w1, acc[i]);
            acc[i] = fmaf(x.z, w2, acc[i]);
            acc[i] = fmaf(x.w, w3, acc[i]);
        }
    }
    #pragma unroll
    for (int i = 0; i < 8; i++)
        g_part[kc][b0 + bq * 8 + i][h] = acc[i];
}

// ---------------------------------------------------------------------------
// Kernel 2: per-batch scores + masked softmax + context (fused).
// One CTA per batch, 256 threads (8 warps -> 2x the warps of round 4).
// C-tile 128p x 64h; each thread owns an 8p x 4h micro-tile (16 f32x2 acc).
// Register-prefetch pipeline overlaps next-chunk LDG with current compute.
// ---------------------------------------------------------------------------
__global__ void __launch_bounds__(256, 2) score_kernel(
    const float* __restrict__ keys,
    const float* __restrict__ frame,
    const int*   __restrict__ mask,
    const float* __restrict__ W1,
    const float* __restrict__ W2,
    float*       __restrict__ out)
{
    const int b   = blockIdx.x;
    const int tid = threadIdx.x;
    const int tx  = tid & 15;   // h-block: h0 = tx*4
    const int ty  = tid >> 4;   // p-block: p0 = ty*8 (0..15)

    __shared__ __align__(16) float sA[32][132];   // [kk][p] transposed keys
    __shared__ __align__(16) float sB[32][68];    // [kk][h]
    __shared__ float bias_s[HID_];
    __shared__ float w2_s[HID_];
    __shared__ float red[P_][17];
    __shared__ float rtmp[4];
    __shared__ float wsm[P_];

    if (tid < HID_) {
        float s = 0.f;
        #pragma unroll
        for (int c = 0; c < KC_; c++) s += g_part[c][b][tid];
        bias_s[tid] = s;
        w2_s[tid]   = W2[tid];
    }

    u64 acc2[8][2];
    #pragma unroll
    for (int i = 0; i < 8; i++) { acc2[i][0] = 0ull; acc2[i][1] = 0ull; }

    const float* kb = keys + (size_t)b * P_ * KD;

    float4 aP[4], bP[2];
    // preload chunk 0
    #pragma unroll
    for (int i = 0; i < 4; i++) {
        int fid = tid + 256 * i;             // 0..1023
        int p = fid >> 3, kq = (fid & 7) << 2;
        aP[i] = *reinterpret_cast<const float4*>(kb + (size_t)p * KD + kq);
    }
    #pragma unroll
    for (int i = 0; i < 2; i++) {
        int fid = tid + 256 * i;             // 0..511
        int kk = fid >> 4, h4 = (fid & 15) << 2;
        bP[i] = *reinterpret_cast<const float4*>(W1 + (size_t)kk * HID_ + h4);
    }

    for (int c = 0; c < 16; c++) {
        __syncthreads();   // previous chunk fully consumed
        // commit prefetched tiles to smem
        #pragma unroll
        for (int i = 0; i < 4; i++) {
            int fid = tid + 256 * i;
            int p = fid >> 3, kq = (fid & 7) << 2;
            sA[kq + 0][p] = aP[i].x; sA[kq + 1][p] = aP[i].y;
            sA[kq + 2][p] = aP[i].z; sA[kq + 3][p] = aP[i].w;
        }
        #pragma unroll
        for (int i = 0; i < 2; i++) {
            int fid = tid + 256 * i;
            int kk = fid >> 4, h4 = (fid & 15) << 2;
            *reinterpret_cast<float4*>(&sB[kk][h4]) = bP[i];
        }
        __syncthreads();
        // prefetch next chunk
        if (c < 15) {
            int k0 = (c + 1) * 32;
            #pragma unroll
            for (int i = 0; i < 4; i++) {
                int fid = tid + 256 * i;
                int p = fid >> 3, kq = (fid & 7) << 2;
                aP[i] = *reinterpret_cast<const float4*>(kb + (size_t)p * KD + k0 + kq);
            }
            #pragma unroll
            for (int i = 0; i < 2; i++) {
                int fid = tid + 256 * i;
                int kk = fid >> 4, h4 = (fid & 15) << 2;
                bP[i] = *reinterpret_cast<const float4*>(W1 + (size_t)(k0 + kk) * HID_ + h4);
            }
        }
        // compute 32 kk steps
        #pragma unroll 8
        for (int kk = 0; kk < 32; kk++) {
            float4 a0 = *reinterpret_cast<const float4*>(&sA[kk][ty << 3]);
            float4 a1 = *reinterpret_cast<const float4*>(&sA[kk][(ty << 3) + 4]);
            ulonglong2 bq = *reinterpret_cast<const ulonglong2*>(&sB[kk][tx << 2]);
            u64 bv0 = bq.x, bv1 = bq.y;
            u64 av[8] = {dup2(a0.x), dup2(a0.y), dup2(a0.z), dup2(a0.w),
                         dup2(a1.x), dup2(a1.y), dup2(a1.z), dup2(a1.w)};
            #pragma unroll
            for (int i = 0; i < 8; i++) {
                acc2[i][0] = ffma2(av[i], bv0, acc2[i][0]);
                acc2[i][1] = ffma2(av[i], bv1, acc2[i][1]);
            }
        }
    }

    // Epilogue: bias + relu + W2 partial dot over this thread's 4 h values
    const int h0 = tx << 2;
    #pragma unroll
    for (int i = 0; i < 8; i++) {
        float l0, h1, l2, h3;
        unpack2(acc2[i][0], l0, h1);
        unpack2(acc2[i][1], l2, h3);
        float v0 = l0 + bias_s[h0 + 0];
        float v1 = h1 + bias_s[h0 + 1];
        float v2 = l2 + bias_s[h0 + 2];
        float v3 = h3 + bias_s[h0 + 3];
        float s  = fmaf(fmaxf(v0, 0.f), w2_s[h0 + 0], 0.f);
        s = fmaf(fmaxf(v1, 0.f), w2_s[h0 + 1], s);
        s = fmaf(fmaxf(v2, 0.f), w2_s[h0 + 2], s);
        s = fmaf(fmaxf(v3, 0.f), w2_s[h0 + 3], s);
        red[(ty << 3) + i][tx] = s;
    }
    __syncthreads();

    // scores for p = tid (first 128 threads = warps 0-3), masked softmax
    float score = -CUDART_INF_F;
    int mv = 0;
    if (tid < P_) {
        float s = 0.f;
        #pragma unroll
        for (int x = 0; x < 16; x++) s += red[tid][x];
        mv = mask[b * P_ + tid];
        score = mv ? s : -CUDART_INF_F;
    }
    float m = score;
    #pragma unroll
    for (int o = 16; o > 0; o >>= 1)
        m = fmaxf(m, __shfl_xor_sync(0xffffffffu, m, o));
    if (tid < P_ && (tid & 31) == 0) rtmp[tid >> 5] = m;
    __syncthreads();
    float mx = fmaxf(fmaxf(rtmp[0], rtmp[1]), fmaxf(rtmp[2], rtmp[3]));
    __syncthreads();

    float e = (tid < P_ && mv) ? expf(score - mx) : 0.f;
    float ssum = e;
    #pragma unroll
    for (int o = 16; o > 0; o >>= 1)
        ssum += __shfl_xor_sync(0xffffffffu, ssum, o);
    if (tid < P_ && (tid & 31) == 0) rtmp[tid >> 5] = ssum;
    __syncthreads();
    float total = rtmp[0] + rtmp[1] + rtmp[2] + rtmp[3];

    float* weights_out = out + (size_t)B_ * EMB;
    if (tid < P_) {
        float wv = e / total;
        weights_out[b * P_ + tid] = wv;
        wsm[tid] = wv;
    }
    __syncthreads();

    // Fused context: thread t -> cols 2t, 2t+1 (keys L2-hot from GEMM pass)
    float cx = 0.f, cy = 0.f;
    const float* kcol = kb + 2 * tid;
    #pragma unroll 8
    for (int p = 0; p < P_; p++) {
        float2 kv = *reinterpret_cast<const float2*>(kcol + (size_t)p * KD);
        float wp = wsm[p];
        cx = fmaf(wp, kv.x, cx);
        cy = fmaf(wp, kv.y, cy);
    }
    float* ob = out + (size_t)b * EMB;
    *reinterpret_cast<float2*>(ob + 2 * tid) = make_float2(cx, cy);

    // frame concat: 1024 floats = 256 float4, one per thread
    const float* fb = frame + (size_t)b * (2 * HF_);
    *reinterpret_cast<float4*>(ob + KD + 4 * tid) =
        *reinterpret_cast<const float4*>(fb + 4 * tid);
}

// ---------------------------------------------------------------------------
extern "C" void kernel_launch(void* const* d_in, const int* in_sizes, int n_in,
                              void* d_out, int out_size)
{
    const float* query = (const float*)d_in[0];   // (256,1,1024)
    const float* keys  = (const float*)d_in[1];   // (256,128,512)
    const float* frame = (const float*)d_in[2];   // (256,1,1024)
    const int*   mask  = (const int*)  d_in[3];   // (256,128)
    const float* W1    = (const float*)d_in[4];   // (2560,64)
    const float* W2    = (const float*)d_in[5];   // (64,1)

    float* out = (float*)d_out;

    dim3 bgrid(KC_, BG_);
    bias_kernel <<<bgrid, 256>>>(query, frame, W1);
    score_kernel<<<B_,    256>>>(keys, frame, mask, W1, W2, out);
}

// round 14
// speedup vs baseline: 1.8451x; 1.0151x over previous
#include <cuda_runtime.h>
#include <math_constants.h>

// Problem constants
#define B_   256
#define P_   128
#define KD   512
#define HE_  1024
#define HF_  512
#define HID_ 64
#define EMB  (KD + 2*HF_)   // 1536

#define KC_  16   // bias split-k chunks of 128 over 2048
#define BG_  8

typedef unsigned long long u64;
typedef unsigned int u32;

// Scratch: split-k partials for bias[b][h] = x_b @ W1qf
__device__ float g_part[KC_][B_][HID_];

__device__ __forceinline__ u64 ffma2(u64 a, u64 b, u64 c) {
    u64 d;
    asm("fma.rn.f32x2 %0, %1, %2, %3;" : "=l"(d) : "l"(a), "l"(b), "l"(c));
    return d;
}
__device__ __forceinline__ u64 dup2(float x) {
    u64 d; unsigned r = __float_as_uint(x);
    asm("mov.b64 %0, {%1, %1};" : "=l"(d) : "r"(r));
    return d;
}
__device__ __forceinline__ void unpack2(u64 v, float& lo, float& hi) {
    unsigned l, h;
    asm("mov.b64 {%0, %1}, %2;" : "=r"(l), "=r"(h) : "l"(v));
    lo = __uint_as_float(l); hi = __uint_as_float(h);
}

// ---------------------------------------------------------------------------
// Kernel 1: split-K bias partials (unchanged — proven, ~3us).
// ---------------------------------------------------------------------------
__global__ void __launch_bounds__(256) bias_kernel(
    const float* __restrict__ query,
    const float* __restrict__ frame,
    const float* __restrict__ W1)
{
    const int kc = blockIdx.x;
    const int bg = blockIdx.y;
    const int j0 = kc * 128;
    const int b0 = bg * 32;
    const int tid = threadIdx.x;

    __shared__ __align__(16) float ws[128][HID_];
    __shared__ __align__(16) float xs[32][128];

    {
        const float4* src = reinterpret_cast<const float4*>(W1 + (size_t)(KD + j0) * HID_);
        float4* dst = reinterpret_cast<float4*>(&ws[0][0]);
        #pragma unroll
        for (int i = 0; i < 8; i++) dst[tid + 256 * i] = src[tid + 256 * i];
    }
    {
        const float* xsrc = (j0 < HE_) ? (query + (size_t)b0 * HE_ + j0)
                                       : (frame + (size_t)b0 * (2 * HF_) + (j0 - HE_));
        #pragma unroll
        for (int i = 0; i < 4; i++) {
            int fid = tid + 256 * i;
            int r = fid >> 5, c4 = (fid & 31) << 2;
            *reinterpret_cast<float4*>(&xs[r][c4]) =
                *reinterpret_cast<const float4*>(xsrc + (size_t)r * 1024 + c4);
        }
    }
    __syncthreads();

    const int h  = tid & 63;
    const int bq = tid >> 6;

    float acc[8];
    #pragma unroll
    for (int i = 0; i < 8; i++) acc[i] = 0.f;

    for (int kk0 = 0; kk0 < 128; kk0 += 4) {
        float w0 = ws[kk0 + 0][h], w1 = ws[kk0 + 1][h];
        float w2 = ws[kk0 + 2][h], w3 = ws[kk0 + 3][h];
        #pragma unroll
        for (int i = 0; i < 8; i++) {
            float4 x = *reinterpret_cast<const float4*>(&xs[bq * 8 + i][kk0]);
            acc[i] = fmaf(x.x, w0, acc[i]);
            acc[i] = fmaf(x.y, w1, acc[i]);
            acc[i] = fmaf(x.z, w2, acc[i]);
            acc[i] = fmaf(x.w, w3, acc[i]);
        }
    }
    #pragma unroll
    for (int i = 0; i < 8; i++)
        g_part[kc][b0 + bq * 8 + i][h] = acc[i];
}

// ---------------------------------------------------------------------------
// Dynamic smem layout for score_kernel (double-buffered stages)
// ---------------------------------------------------------------------------
#define SA_STRIDE 132
#define SB_STRIDE 68
#define OFF_SA(s)  ((s) * 16896)                 // 32*132*4 each
#define OFF_SB(s)  (33792 + (s) * 8704)          // 32*68*4 each
#define OFF_RED    51200                         // 128*17*4 = 8704
#define OFF_BIAS   59904                         // 64 f32
#define OFF_W2     60160                         // 64 f32
#define OFF_RTMP   60416                         // 4 f32
#define OFF_WSM    60432                         // 128 f32
#define SMEM_DYN   61440

// ---------------------------------------------------------------------------
// Kernel 2: per-batch scores + masked softmax + context (fused).
// One CTA per batch, 256 threads. C-tile 128p x 64h; each thread owns an
// 8p x 4h micro-tile as 16 f32x2 accumulators packed along p-pairs:
// a-operands come pre-packed from sA (no dup), only 4 b-dups per kk.
// Double-buffered smem stages -> single __syncthreads per K chunk.
// ---------------------------------------------------------------------------
__global__ void __launch_bounds__(256, 2) score_kernel(
    const float* __restrict__ keys,
    const float* __restrict__ frame,
    const int*   __restrict__ mask,
    const float* __restrict__ W1,
    const float* __restrict__ W2,
    float*       __restrict__ out)
{
    extern __shared__ __align__(16) char smem[];
    const int b   = blockIdx.x;
    const int tid = threadIdx.x;
    const int tx  = tid & 15;   // h-block: h0 = tx*4
    const int ty  = tid >> 4;   // p-block: p0 = ty*8 (0..15)

    float* bias_s = (float*)(smem + OFF_BIAS);
    float* w2_s   = (float*)(smem + OFF_W2);
    float* rtmp   = (float*)(smem + OFF_RTMP);
    float* wsm    = (float*)(smem + OFF_WSM);

    if (tid < HID_) {
        float s = 0.f;
        #pragma unroll
        for (int c = 0; c < KC_; c++) s += g_part[c][b][tid];
        bias_s[tid] = s;
        w2_s[tid]   = W2[tid];
    }

    // acc2[hj][pi]: f32x2 over p-pair (2pi, 2pi+1) at h = tx*4 + hj
    u64 acc2[4][4];
    #pragma unroll
    for (int j = 0; j < 4; j++)
        #pragma unroll
        for (int i = 0; i < 4; i++) acc2[j][i] = 0ull;

    const float* kb = keys + (size_t)b * P_ * KD;

    float4 aP[4], bP[2];
    // LDG chunk 0 -> regs
    #pragma unroll
    for (int i = 0; i < 4; i++) {
        int fid = tid + 256 * i;
        int p = fid >> 3, kq = (fid & 7) << 2;
        aP[i] = *reinterpret_cast<const float4*>(kb + (size_t)p * KD + kq);
    }
    #pragma unroll
    for (int i = 0; i < 2; i++) {
        int fid = tid + 256 * i;
        int kk = fid >> 4, h4 = (fid & 15) << 2;
        bP[i] = *reinterpret_cast<const float4*>(W1 + (size_t)kk * HID_ + h4);
    }
    // STS chunk 0 -> stage 0
    {
        float* sA0 = (float*)(smem + OFF_SA(0));
        float* sB0 = (float*)(smem + OFF_SB(0));
        #pragma unroll
        for (int i = 0; i < 4; i++) {
            int fid = tid + 256 * i;
            int p = fid >> 3, kq = (fid & 7) << 2;
            sA0[(kq + 0) * SA_STRIDE + p] = aP[i].x;
            sA0[(kq + 1) * SA_STRIDE + p] = aP[i].y;
            sA0[(kq + 2) * SA_STRIDE + p] = aP[i].z;
            sA0[(kq + 3) * SA_STRIDE + p] = aP[i].w;
        }
        #pragma unroll
        for (int i = 0; i < 2; i++) {
            int fid = tid + 256 * i;
            int kk = fid >> 4, h4 = (fid & 15) << 2;
            *reinterpret_cast<float4*>(&sB0[kk * SB_STRIDE + h4]) = bP[i];
        }
    }
    // LDG chunk 1 -> regs
    #pragma unroll
    for (int i = 0; i < 4; i++) {
        int fid = tid + 256 * i;
        int p = fid >> 3, kq = (fid & 7) << 2;
        aP[i] = *reinterpret_cast<const float4*>(kb + (size_t)p * KD + 32 + kq);
    }
    #pragma unroll
    for (int i = 0; i < 2; i++) {
        int fid = tid + 256 * i;
        int kk = fid >> 4, h4 = (fid & 15) << 2;
        bP[i] = *reinterpret_cast<const float4*>(W1 + (size_t)(32 + kk) * HID_ + h4);
    }
    __syncthreads();

    for (int c = 0; c < 16; c++) {
        const int s = c & 1;
        // STS chunk c+1 (in regs) -> stage s^1
        if (c < 15) {
            float* sAn = (float*)(smem + OFF_SA(s ^ 1));
            float* sBn = (float*)(smem + OFF_SB(s ^ 1));
            #pragma unroll
            for (int i = 0; i < 4; i++) {
                int fid = tid + 256 * i;
                int p = fid >> 3, kq = (fid & 7) << 2;
                sAn[(kq + 0) * SA_STRIDE + p] = aP[i].x;
                sAn[(kq + 1) * SA_STRIDE + p] = aP[i].y;
                sAn[(kq + 2) * SA_STRIDE + p] = aP[i].z;
                sAn[(kq + 3) * SA_STRIDE + p] = aP[i].w;
            }
            #pragma unroll
            for (int i = 0; i < 2; i++) {
                int fid = tid + 256 * i;
                int kk = fid >> 4, h4 = (fid & 15) << 2;
                *reinterpret_cast<float4*>(&sBn[kk * SB_STRIDE + h4]) = bP[i];
            }
        }
        // LDG chunk c+2 -> regs
        if (c < 14) {
            int k0 = (c + 2) * 32;
            #pragma unroll
            for (int i = 0; i < 4; i++) {
                int fid = tid + 256 * i;
                int p = fid >> 3, kq = (fid & 7) << 2;
                aP[i] = *reinterpret_cast<const float4*>(kb + (size_t)p * KD + k0 + kq);
            }
            #pragma unroll
            for (int i = 0; i < 2; i++) {
                int fid = tid + 256 * i;
                int kk = fid >> 4, h4 = (fid & 15) << 2;
                bP[i] = *reinterpret_cast<const float4*>(W1 + (size_t)(k0 + kk) * HID_ + h4);
            }
        }
        // compute stage s
        const float* sA = (const float*)(smem + OFF_SA(s));
        const float* sB = (const float*)(smem + OFF_SB(s));
        #pragma unroll 8
        for (int kk = 0; kk < 32; kk++) {
            ulonglong2 a01 = *reinterpret_cast<const ulonglong2*>(&sA[kk * SA_STRIDE + (ty << 3)]);
            ulonglong2 a23 = *reinterpret_cast<const ulonglong2*>(&sA[kk * SA_STRIDE + (ty << 3) + 4]);
            float4 bf = *reinterpret_cast<const float4*>(&sB[kk * SB_STRIDE + (tx << 2)]);
            u64 b0 = dup2(bf.x), b1 = dup2(bf.y), b2 = dup2(bf.z), b3 = dup2(bf.w);
            u64 ap0 = a01.x, ap1 = a01.y, ap2 = a23.x, ap3 = a23.y;
            acc2[0][0] = ffma2(ap0, b0, acc2[0][0]);
            acc2[0][1] = ffma2(ap1, b0, acc2[0][1]);
            acc2[0][2] = ffma2(ap2, b0, acc2[0][2]);
            acc2[0][3] = ffma2(ap3, b0, acc2[0][3]);
            acc2[1][0] = ffma2(ap0, b1, acc2[1][0]);
            acc2[1][1] = ffma2(ap1, b1, acc2[1][1]);
            acc2[1][2] = ffma2(ap2, b1, acc2[1][2]);
            acc2[1][3] = ffma2(ap3, b1, acc2[1][3]);
            acc2[2][0] = ffma2(ap0, b2, acc2[2][0]);
            acc2[2][1] = ffma2(ap1, b2, acc2[2][1]);
            acc2[2][2] = ffma2(ap2, b2, acc2[2][2]);
            acc2[2][3] = ffma2(ap3, b2, acc2[2][3]);
            acc2[3][0] = ffma2(ap0, b3, acc2[3][0]);
            acc2[3][1] = ffma2(ap1, b3, acc2[3][1]);
            acc2[3][2] = ffma2(ap2, b3, acc2[3][2]);
            acc2[3][3] = ffma2(ap3, b3, acc2[3][3]);
        }
        __syncthreads();
    }

    // Epilogue: bias + relu + W2 partial dot. lo(acc)=p even, hi=p odd.
    float* red = (float*)(smem + OFF_RED);
    const int h0 = tx << 2;
    #pragma unroll
    for (int pi = 0; pi < 4; pi++) {
        float s0 = 0.f, s1 = 0.f;
        #pragma unroll
        for (int hj = 0; hj < 4; hj++) {
            float lo, hi;
            unpack2(acc2[hj][pi], lo, hi);
            float bz = bias_s[h0 + hj];
            float wz = w2_s[h0 + hj];
            s0 = fmaf(fmaxf(lo + bz, 0.f), wz, s0);
            s1 = fmaf(fmaxf(hi + bz, 0.f), wz, s1);
        }
        red[((ty << 3) + 2 * pi)     * 17 + tx] = s0;
        red[((ty << 3) + 2 * pi + 1) * 17 + tx] = s1;
    }
    __syncthreads();

    // scores for p = tid (first 128 threads), masked softmax
    float score = -CUDART_INF_F;
    int mv = 0;
    if (tid < P_) {
        float s = 0.f;
        #pragma unroll
        for (int x = 0; x < 16; x++) s += red[tid * 17 + x];
        mv = mask[b * P_ + tid];
        score = mv ? s : -CUDART_INF_F;
    }
    float m = score;
    #pragma unroll
    for (int o = 16; o > 0; o >>= 1)
        m = fmaxf(m, __shfl_xor_sync(0xffffffffu, m, o));
    if (tid < P_ && (tid & 31) == 0) rtmp[tid >> 5] = m;
    __syncthreads();
    float mx = fmaxf(fmaxf(rtmp[0], rtmp[1]), fmaxf(rtmp[2], rtmp[3]));
    __syncthreads();

    float e = (tid < P_ && mv) ? expf(score - mx) : 0.f;
    float ssum = e;
    #pragma unroll
    for (int o = 16; o > 0; o >>= 1)
        ssum += __shfl_xor_sync(0xffffffffu, ssum, o);
    if (tid < P_ && (tid & 31) == 0) rtmp[tid >> 5] = ssum;
    __syncthreads();
    float total = rtmp[0] + rtmp[1] + rtmp[2] + rtmp[3];

    float* weights_out = out + (size_t)B_ * EMB;
    if (tid < P_) {
        float wv = e / total;
        weights_out[b * P_ + tid] = wv;
        wsm[tid] = wv;
    }
    __syncthreads();

    // Fused context: thread t -> cols 2t, 2t+1 (keys L2-hot from GEMM pass)
    float cx = 0.f, cy = 0.f;
    const float* kcol = kb + 2 * tid;
    #pragma unroll 8
    for (int p = 0; p < P_; p++) {
        float2 kv = *reinterpret_cast<const float2*>(kcol + (size_t)p * KD);
        float wp = wsm[p];
        cx = fmaf(wp, kv.x, cx);
        cy = fmaf(wp, kv.y, cy);
    }
    float* ob = out + (size_t)b * EMB;
    *reinterpret_cast<float2*>(ob + 2 * tid) = make_float2(cx, cy);

    // frame concat: 1024 floats = 256 float4, one per thread
    const float* fb = frame + (size_t)b * (2 * HF_);
    *reinterpret_cast<float4*>(ob + KD + 4 * tid) =
        *reinterpret_cast<const float4*>(fb + 4 * tid);
}

// ---------------------------------------------------------------------------
extern "C" void kernel_launch(void* const* d_in, const int* in_sizes, int n_in,
                              void* d_out, int out_size)
{
    const float* query = (const float*)d_in[0];   // (256,1,1024)
    const float* keys  = (const float*)d_in[1];   // (256,128,512)
    const float* frame = (const float*)d_in[2];   // (256,1,1024)
    const int*   mask  = (const int*)  d_in[3];   // (256,128)
    const float* W1    = (const float*)d_in[4];   // (2560,64)
    const float* W2    = (const float*)d_in[5];   // (64,1)

    float* out = (float*)d_out;

    cudaFuncSetAttribute(score_kernel,
                         cudaFuncAttributeMaxDynamicSharedMemorySize, SMEM_DYN);

    dim3 bgrid(KC_, BG_);
    bias_kernel <<<bgrid, 256>>>(query, frame, W1);
    score_kernel<<<B_, 256, SMEM_DYN>>>(keys, frame, mask, W1, W2, out);
}